// round 1
// baseline (speedup 1.0000x reference)
#include <cuda_runtime.h>
#include <cuda_bf16.h>

#define NBINS 10

// Scratch: per-bin accumulators (device globals — no allocation allowed).
__device__ float        g_bin_sum[NBINS];
__device__ unsigned int g_bin_cnt[NBINS];

__global__ void ghmc_zero_kernel() {
    int t = threadIdx.x;
    if (t < NBINS) {
        g_bin_sum[t] = 0.0f;
        g_bin_cnt[t] = 0u;
    }
}

// Process one scalar element: compute bce + bin index, accumulate into
// register-resident per-thread bins via predicated adds.
__device__ __forceinline__ void ghmc_elem(float x, float t, float w,
                                          float* __restrict__ sum,
                                          float* __restrict__ cnt) {
    float ax = fabsf(x);
    float e  = __expf(-ax);           // e = exp(-|x|) in (0,1]
    float d  = 1.0f + e;              // in (1,2]
    float r  = __fdividef(1.0f, d);   // 1/(1+e)
    float sig = (x >= 0.0f) ? r : e * r;   // sigmoid(x)
    float g  = fabsf(sig - t);
    float fb = floorf(g * 10.0f);
    fb = fminf(fmaxf(fb, 0.0f), 9.0f);     // bin index as float, 0..9
    // stable BCE-with-logits: max(x,0) - x*t + log(1 + exp(-|x|))
    float bce = fmaxf(x, 0.0f) - x * t + __logf(d);
    bool  valid = (w > 0.0f);
    float bv = valid ? bce  : 0.0f;
    float cv = valid ? 1.0f : 0.0f;
#pragma unroll
    for (int b = 0; b < NBINS; b++) {
        asm volatile(
            "{\n\t"
            ".reg .pred p;\n\t"
            "setp.eq.f32 p, %2, %3;\n\t"
            "@p add.f32 %0, %0, %4;\n\t"
            "@p add.f32 %1, %1, %5;\n\t"
            "}"
            : "+f"(sum[b]), "+f"(cnt[b])
            : "f"(fb), "f"((float)b), "f"(bv), "f"(cv));
    }
}

__global__ void __launch_bounds__(256)
ghmc_main_kernel(const float4* __restrict__ pred,
                 const float4* __restrict__ targ,
                 const float4* __restrict__ lw,
                 int n4) {
    float sum[NBINS];
    float cnt[NBINS];
#pragma unroll
    for (int b = 0; b < NBINS; b++) { sum[b] = 0.0f; cnt[b] = 0.0f; }

    int stride = gridDim.x * blockDim.x;
    for (int i = blockIdx.x * blockDim.x + threadIdx.x; i < n4; i += stride) {
        float4 p = pred[i];
        float4 t = targ[i];
        float4 w = lw[i];
        ghmc_elem(p.x, t.x, w.x, sum, cnt);
        ghmc_elem(p.y, t.y, w.y, sum, cnt);
        ghmc_elem(p.z, t.z, w.z, sum, cnt);
        ghmc_elem(p.w, t.w, w.w, sum, cnt);
    }

    // Warp butterfly reduce all 10 bins (sums + counts).
#pragma unroll
    for (int b = 0; b < NBINS; b++) {
#pragma unroll
        for (int off = 16; off > 0; off >>= 1) {
            sum[b] += __shfl_xor_sync(0xffffffffu, sum[b], off);
            cnt[b] += __shfl_xor_sync(0xffffffffu, cnt[b], off);
        }
    }

    __shared__ float s_sum[NBINS];
    __shared__ float s_cnt[NBINS];
    if (threadIdx.x < NBINS) { s_sum[threadIdx.x] = 0.0f; s_cnt[threadIdx.x] = 0.0f; }
    __syncthreads();

    if ((threadIdx.x & 31) == 0) {
#pragma unroll
        for (int b = 0; b < NBINS; b++) {
            atomicAdd(&s_sum[b], sum[b]);
            atomicAdd(&s_cnt[b], cnt[b]);
        }
    }
    __syncthreads();

    if (threadIdx.x < NBINS) {
        atomicAdd(&g_bin_sum[threadIdx.x], s_sum[threadIdx.x]);
        // block-level counts are small exact integers in fp32
        atomicAdd(&g_bin_cnt[threadIdx.x], (unsigned int)(s_cnt[threadIdx.x] + 0.5f));
    }
}

__global__ void ghmc_final_kernel(float* __restrict__ out) {
    if (threadIdx.x == 0 && blockIdx.x == 0) {
        float total = 0.0f;
        int   n = 0;
#pragma unroll
        for (int b = 0; b < NBINS; b++) {
            unsigned int c = g_bin_cnt[b];
            if (c > 0u) {
                n += 1;
                total += g_bin_sum[b] / (float)c;
            }
        }
        out[0] = (n > 0) ? (total / (float)n) : 0.0f;
    }
}

extern "C" void kernel_launch(void* const* d_in, const int* in_sizes, int n_in,
                              void* d_out, int out_size) {
    const float4* pred = (const float4*)d_in[0];
    const float4* targ = (const float4*)d_in[1];
    const float4* lw   = (const float4*)d_in[2];
    float* out = (float*)d_out;

    int n  = in_sizes[0];     // 41,943,040 (divisible by 4)
    int n4 = n >> 2;

    ghmc_zero_kernel<<<1, 32>>>();

    const int threads = 256;
    int blocks = (n4 + threads - 1) / threads;
    if (blocks > 1184) blocks = 1184;   // 148 SMs * 8
    ghmc_main_kernel<<<blocks, threads>>>(pred, targ, lw, n4);

    ghmc_final_kernel<<<1, 32>>>(out);
}